// round 1
// baseline (speedup 1.0000x reference)
#include <cuda_runtime.h>
#include <cuda_bf16.h>
#include <math.h>

// ---------------- problem constants ----------------
#define BB 8
#define TT 2048
#define DD 128
#define HH 4
#define HD 32          // hd
#define DH 64          // 2*hd per head
#define NTOK (BB*TT)   // 16384
#define SCALE 0.17677669529663687f   // 1/sqrt(32)
#define LAMBDA_INIT 0.8f
#define LN_EPS 1e-5f
#define BAND 96        // key band half-width (error ~1e-13, see analysis)

// ---------------- scratch (device globals; no allocs allowed) ----------------
__device__ float g_xnorm[NTOK * DD];          // 8 MB
__device__ float g_Q[BB*HH*TT*DH];            // 16 MB  [bh][t][64] (q1:0..31, q2:32..63)
__device__ float g_K[BB*HH*TT*DH];            // 16 MB
__device__ float g_V[BB*HH*TT*DH];            // 16 MB
__device__ float g_O[NTOK * 256];             // 16 MB  [token][h*64+dim]

// ---------------- helpers ----------------
__device__ __forceinline__ float redmax8(float v){
    v = fmaxf(v, __shfl_xor_sync(0xffffffffu, v, 1));
    v = fmaxf(v, __shfl_xor_sync(0xffffffffu, v, 2));
    v = fmaxf(v, __shfl_xor_sync(0xffffffffu, v, 4));
    return v;
}
__device__ __forceinline__ float redsum8(float v){
    v += __shfl_xor_sync(0xffffffffu, v, 1);
    v += __shfl_xor_sync(0xffffffffu, v, 2);
    v += __shfl_xor_sync(0xffffffffu, v, 4);
    return v;
}

// ================= K0: layernorm over D=128 =================
__global__ __launch_bounds__(256) void ln_kernel(const float* __restrict__ x,
                                                 const float* __restrict__ w,
                                                 const float* __restrict__ b){
    int token = blockIdx.x * 8 + threadIdx.y;
    int lane  = threadIdx.x;
    const float4* xr = (const float4*)(x + (size_t)token * DD);
    float4 v = xr[lane];
    float s = v.x + v.y + v.z + v.w;
    #pragma unroll
    for (int o = 16; o; o >>= 1) s += __shfl_xor_sync(0xffffffffu, s, o);
    float mu = s * (1.0f / DD);
    float dx0 = v.x - mu, dx1 = v.y - mu, dx2 = v.z - mu, dx3 = v.w - mu;
    float sq = dx0*dx0 + dx1*dx1 + dx2*dx2 + dx3*dx3;
    #pragma unroll
    for (int o = 16; o; o >>= 1) sq += __shfl_xor_sync(0xffffffffu, sq, o);
    float rstd = rsqrtf(sq * (1.0f / DD) + LN_EPS);
    float4 wv = ((const float4*)w)[lane];
    float4 bv = ((const float4*)b)[lane];
    float4 out;
    out.x = dx0 * rstd * wv.x + bv.x;
    out.y = dx1 * rstd * wv.y + bv.y;
    out.z = dx2 * rstd * wv.z + bv.z;
    out.w = dx3 * rstd * wv.w + bv.w;
    ((float4*)(g_xnorm + (size_t)token * DD))[lane] = out;
}

// ================= K1: QKV GEMM (16384 x 768 x 128) =================
// BM=64, BN=64, BK=32; grid (256, 12); block 256; 4x4 microtile.
// Epilogue scatters into per-head [bh][t][64] layouts.
__global__ __launch_bounds__(256) void qkv_gemm(const float* __restrict__ wq,
                                                const float* __restrict__ wk,
                                                const float* __restrict__ wv){
    __shared__ float As[64*33];
    __shared__ float Bs[32*64];
    int brow = blockIdx.x, bc = blockIdx.y;
    int tid = threadIdx.x;
    int tr = tid >> 4, tc = tid & 15;
    const float* W = (bc < 4) ? wq : (bc < 8 ? wk : wv);
    int colbase = (bc & 3) * 64;
    float acc[4][4] = {};

    for (int kc = 0; kc < 4; kc++){
        #pragma unroll
        for (int f = tid; f < 512; f += 256){
            int r = f >> 3, c4 = f & 7;
            float4 v = *(const float4*)(g_xnorm + (size_t)(brow*64 + r)*DD + kc*32 + c4*4);
            float* d = As + r*33 + c4*4;
            d[0]=v.x; d[1]=v.y; d[2]=v.z; d[3]=v.w;
        }
        #pragma unroll
        for (int f = tid; f < 512; f += 256){
            int kr = f >> 4, c4 = f & 15;
            float4 v = *(const float4*)(W + (size_t)(kc*32 + kr)*256 + colbase + c4*4);
            *(float4*)(Bs + kr*64 + c4*4) = v;
        }
        __syncthreads();
        #pragma unroll
        for (int k = 0; k < 32; k++){
            float a[4];
            #pragma unroll
            for (int i = 0; i < 4; i++) a[i] = As[(tr*4+i)*33 + k];
            float4 bvec = *(const float4*)(Bs + k*64 + tc*4);
            float bb[4] = {bvec.x, bvec.y, bvec.z, bvec.w};
            #pragma unroll
            for (int i = 0; i < 4; i++)
                #pragma unroll
                for (int j = 0; j < 4; j++)
                    acc[i][j] += a[i] * bb[j];
        }
        __syncthreads();
    }

    int mat = bc >> 2, head = bc & 3;
    float* dst = (mat == 0) ? g_Q : (mat == 1 ? g_K : g_V);
    #pragma unroll
    for (int i = 0; i < 4; i++){
        int token = brow*64 + tr*4 + i;
        int b_ = token >> 11, t = token & (TT-1);
        float4 v = make_float4(acc[i][0], acc[i][1], acc[i][2], acc[i][3]);
        *(float4*)(dst + ((size_t)((b_*HH + head)*TT + t))*DH + tc*4) = v;
    }
}

// ================= K2: banded dual-softmax flash attention =================
// grid (T/64=32, B*H=32); block 128. Thread (tr=tid>>3, tc=tid&7):
//   rows tr*4..+3, score cols tc*4..+3, output dims {tc + 8*dj}.
#define SQ_STRIDE 65
#define SK_STRIDE 33
#define SP_STRIDE 65
#define SM_Q1 0
#define SM_Q2 (32*SQ_STRIDE)
#define SM_K1 (2*32*SQ_STRIDE)
#define SM_K2 (SM_K1 + 32*SK_STRIDE)
#define SM_V  (SM_K2 + 32*SK_STRIDE)
#define SM_P1 (SM_V + 32*64)
#define SM_P2 (SM_P1 + 32*SP_STRIDE)
#define ATTN_SMEM_FLOATS (SM_P2 + 32*SP_STRIDE)
#define ATTN_SMEM_BYTES (ATTN_SMEM_FLOATS * 4)

__global__ __launch_bounds__(128) void attn_kernel(
        const float* __restrict__ lq1, const float* __restrict__ lk1,
        const float* __restrict__ lq2, const float* __restrict__ lk2,
        const float* __restrict__ sig_s_p, const float* __restrict__ sig_n_p,
        const float* __restrict__ hnw, const float* __restrict__ hnb){
    extern __shared__ float sm[];
    float* sq1 = sm + SM_Q1;   // [32 d][65]  q1 transposed
    float* sq2 = sm + SM_Q2;
    float* sk1 = sm + SM_K1;   // [32 d][33]  k1 transposed
    float* sk2 = sm + SM_K2;
    float* sv  = sm + SM_V;    // [32 key][64 dim]
    float* sp1 = sm + SM_P1;   // [32 key][65 row]  P transposed
    float* sp2 = sm + SM_P2;

    int bh = blockIdx.y;
    int q0 = blockIdx.x * 64;
    int tid = threadIdx.x;
    int tr4 = (tid >> 3) * 4;
    int tc  = tid & 7;
    int tc4 = tc * 4;

    const float* Qb = g_Q + (size_t)bh * TT * DH;
    const float* Kb = g_K + (size_t)bh * TT * DH;
    const float* Vb = g_V + (size_t)bh * TT * DH;

    // load Q tile (transposed, padded)
    for (int i = tid; i < 64*16; i += 128){
        int r = i >> 4, c4 = i & 15;
        float4 v = *(const float4*)(Qb + (size_t)(q0 + r)*DH + c4*4);
        float vv[4] = {v.x, v.y, v.z, v.w};
        if (c4 < 8){
            #pragma unroll
            for (int j = 0; j < 4; j++) sq1[(c4*4 + j)*SQ_STRIDE + r] = vv[j];
        } else {
            #pragma unroll
            for (int j = 0; j < 4; j++) sq2[((c4-8)*4 + j)*SQ_STRIDE + r] = vv[j];
        }
    }

    // lambda scalar (cheap, redundant per thread; all loads hit L1/L2)
    float e1 = 0.f, e2 = 0.f;
    #pragma unroll
    for (int i = 0; i < HD; i++){ e1 += lq1[i]*lk1[i]; e2 += lq2[i]*lk2[i]; }
    float lam = __expf(e1) - __expf(e2) + LAMBDA_INIT;
    float sig_s = fmaxf(sig_s_p[0], 1.0f), sig_n = fmaxf(sig_n_p[0], 1.0f);
    float c1 = -0.5f / (sig_s * sig_s), c2 = -0.5f / (sig_n * sig_n);

    float o1[4][8] = {}, o2[4][8] = {};
    float m1[4], l1[4], m2[4], l2[4];
    #pragma unroll
    for (int i = 0; i < 4; i++){ m1[i] = m2[i] = -1e30f; l1[i] = l2[i] = 0.f; }

    int klo = q0 - BAND; if (klo < 0) klo = 0;
    int khi = q0 + 64 + BAND; if (khi > TT) khi = TT;

    for (int ks = klo; ks < khi; ks += 32){
        __syncthreads();   // prior PV done before overwriting K/V
        // load K (transposed split) and V tiles
        for (int i = tid; i < 32*16; i += 128){
            int kk = i >> 4, c4 = i & 15;
            float4 kv = *(const float4*)(Kb + (size_t)(ks + kk)*DH + c4*4);
            float kvv[4] = {kv.x, kv.y, kv.z, kv.w};
            if (c4 < 8){
                #pragma unroll
                for (int j = 0; j < 4; j++) sk1[(c4*4 + j)*SK_STRIDE + kk] = kvv[j];
            } else {
                #pragma unroll
                for (int j = 0; j < 4; j++) sk2[((c4-8)*4 + j)*SK_STRIDE + kk] = kvv[j];
            }
            float4 vv = *(const float4*)(Vb + (size_t)(ks + kk)*DH + c4*4);
            *(float4*)(sv + kk*64 + c4*4) = vv;
        }
        __syncthreads();

        // scores: S1 = Q1 K1^T, S2 = Q2 K2^T  (64x32 each, 4x4 per thread)
        float s1[4][4] = {}, s2[4][4] = {};
        #pragma unroll 8
        for (int d = 0; d < 32; d++){
            float qa1[4], qa2[4], kb1[4], kb2[4];
            #pragma unroll
            for (int i = 0; i < 4; i++){
                qa1[i] = sq1[d*SQ_STRIDE + tr4 + i];
                qa2[i] = sq2[d*SQ_STRIDE + tr4 + i];
            }
            #pragma unroll
            for (int j = 0; j < 4; j++){
                kb1[j] = sk1[d*SK_STRIDE + tc4 + j];
                kb2[j] = sk2[d*SK_STRIDE + tc4 + j];
            }
            #pragma unroll
            for (int i = 0; i < 4; i++)
                #pragma unroll
                for (int j = 0; j < 4; j++){
                    s1[i][j] += qa1[i]*kb1[j];
                    s2[i][j] += qa2[i]*kb2[j];
                }
        }

        // bias + online softmax stats + write P
        #pragma unroll
        for (int i = 0; i < 4; i++){
            int qrow = q0 + tr4 + i;
            float rmax1 = -1e30f, rmax2 = -1e30f;
            #pragma unroll
            for (int j = 0; j < 4; j++){
                float rel = (float)(ks + tc4 + j - qrow);
                float r2 = rel * rel;
                s1[i][j] = s1[i][j]*SCALE + r2*c1;
                s2[i][j] = s2[i][j]*SCALE + r2*c2;
                rmax1 = fmaxf(rmax1, s1[i][j]);
                rmax2 = fmaxf(rmax2, s2[i][j]);
            }
            rmax1 = redmax8(rmax1);
            rmax2 = redmax8(rmax2);
            float mn1 = fmaxf(m1[i], rmax1), mn2 = fmaxf(m2[i], rmax2);
            float sc1 = __expf(m1[i] - mn1), sc2 = __expf(m2[i] - mn2);
            m1[i] = mn1; m2[i] = mn2;
            float rs1 = 0.f, rs2 = 0.f;
            #pragma unroll
            for (int j = 0; j < 4; j++){
                float p1 = __expf(s1[i][j] - mn1);
                float p2 = __expf(s2[i][j] - mn2);
                rs1 += p1; rs2 += p2;
                sp1[(tc4 + j)*SP_STRIDE + tr4 + i] = p1;
                sp2[(tc4 + j)*SP_STRIDE + tr4 + i] = p2;
            }
            rs1 = redsum8(rs1);
            rs2 = redsum8(rs2);
            l1[i] = l1[i]*sc1 + rs1;
            l2[i] = l2[i]*sc2 + rs2;
            #pragma unroll
            for (int dj = 0; dj < 8; dj++){ o1[i][dj] *= sc1; o2[i][dj] *= sc2; }
        }
        __syncthreads();

        // PV: o += P @ V  (shared V between both branches)
        #pragma unroll 4
        for (int k = 0; k < 32; k++){
            float vv[8], p1v[4], p2v[4];
            #pragma unroll
            for (int dj = 0; dj < 8; dj++) vv[dj] = sv[k*64 + tc + 8*dj];
            #pragma unroll
            for (int i = 0; i < 4; i++){
                p1v[i] = sp1[k*SP_STRIDE + tr4 + i];
                p2v[i] = sp2[k*SP_STRIDE + tr4 + i];
            }
            #pragma unroll
            for (int i = 0; i < 4; i++)
                #pragma unroll
                for (int dj = 0; dj < 8; dj++){
                    o1[i][dj] += p1v[i]*vv[dj];
                    o2[i][dj] += p2v[i]*vv[dj];
                }
        }
    }

    // epilogue: combine, head-LN over 64 dims, *0.2, write O [token][h*64+dim]
    int b_ = bh >> 2, h = bh & 3;
    #pragma unroll
    for (int i = 0; i < 4; i++){
        float inv1 = 1.0f / l1[i];
        float inv2 = lam / l2[i];
        float ov[8];
        float s = 0.f;
        #pragma unroll
        for (int dj = 0; dj < 8; dj++){
            ov[dj] = o1[i][dj]*inv1 - o2[i][dj]*inv2;
            s += ov[dj];
        }
        s = redsum8(s);
        float mean = s * (1.0f / DH);
        float sq = 0.f;
        #pragma unroll
        for (int dj = 0; dj < 8; dj++){ float d_ = ov[dj] - mean; sq += d_*d_; }
        sq = redsum8(sq);
        float rstd = rsqrtf(sq * (1.0f / DH) + LN_EPS);
        int qrow = q0 + tr4 + i;
        float* Orow = g_O + ((size_t)(b_*TT + qrow))*256 + h*DH;
        #pragma unroll
        for (int dj = 0; dj < 8; dj++){
            int dim = tc + 8*dj;
            float y = ((ov[dj] - mean)*rstd*hnw[dim] + hnb[dim]) * (1.0f - LAMBDA_INIT);
            Orow[dim] = y;
        }
    }
}

// ================= K3: output GEMM (16384 x 128 x 256) + residual =================
__global__ __launch_bounds__(256) void out_gemm(const float* __restrict__ wo,
                                                const float* __restrict__ tokens,
                                                float* __restrict__ out){
    __shared__ float As[64*33];
    __shared__ float Bs[32*64];
    int brow = blockIdx.x, bc = blockIdx.y;  // bc in 0..1
    int tid = threadIdx.x;
    int tr = tid >> 4, tc = tid & 15;
    float acc[4][4] = {};

    for (int kc = 0; kc < 8; kc++){
        #pragma unroll
        for (int f = tid; f < 512; f += 256){
            int r = f >> 3, c4 = f & 7;
            float4 v = *(const float4*)(g_O + (size_t)(brow*64 + r)*256 + kc*32 + c4*4);
            float* d = As + r*33 + c4*4;
            d[0]=v.x; d[1]=v.y; d[2]=v.z; d[3]=v.w;
        }
        #pragma unroll
        for (int f = tid; f < 512; f += 256){
            int kr = f >> 4, c4 = f & 15;
            float4 v = *(const float4*)(wo + (size_t)(kc*32 + kr)*DD + bc*64 + c4*4);
            *(float4*)(Bs + kr*64 + c4*4) = v;
        }
        __syncthreads();
        #pragma unroll
        for (int k = 0; k < 32; k++){
            float a[4];
            #pragma unroll
            for (int i = 0; i < 4; i++) a[i] = As[(tr*4+i)*33 + k];
            float4 bvec = *(const float4*)(Bs + k*64 + tc*4);
            float bb[4] = {bvec.x, bvec.y, bvec.z, bvec.w};
            #pragma unroll
            for (int i = 0; i < 4; i++)
                #pragma unroll
                for (int j = 0; j < 4; j++)
                    acc[i][j] += a[i] * bb[j];
        }
        __syncthreads();
    }

    #pragma unroll
    for (int i = 0; i < 4; i++){
        int token = brow*64 + tr*4 + i;
        int col = bc*64 + tc*4;
        float4 tv = *(const float4*)(tokens + (size_t)token*DD + col);
        float4 v = make_float4(acc[i][0]+tv.x, acc[i][1]+tv.y, acc[i][2]+tv.z, acc[i][3]+tv.w);
        *(float4*)(out + (size_t)token*DD + col) = v;
    }
}

// ================= launch =================
extern "C" void kernel_launch(void* const* d_in, const int* in_sizes, int n_in,
                              void* d_out, int out_size){
    const float* tokens = (const float*)d_in[0];
    const float* ln_w   = (const float*)d_in[1];
    const float* ln_b   = (const float*)d_in[2];
    const float* wq     = (const float*)d_in[3];
    const float* wk     = (const float*)d_in[4];
    const float* wv     = (const float*)d_in[5];
    const float* wo     = (const float*)d_in[6];
    const float* lq1    = (const float*)d_in[7];
    const float* lk1    = (const float*)d_in[8];
    const float* lq2    = (const float*)d_in[9];
    const float* lk2    = (const float*)d_in[10];
    const float* sig_s  = (const float*)d_in[11];
    const float* sig_n  = (const float*)d_in[12];
    const float* hnw    = (const float*)d_in[13];
    const float* hnb    = (const float*)d_in[14];
    float* out = (float*)d_out;

    cudaFuncSetAttribute(attn_kernel, cudaFuncAttributeMaxDynamicSharedMemorySize,
                         ATTN_SMEM_BYTES);

    ln_kernel<<<NTOK/8, dim3(32,8)>>>(tokens, ln_w, ln_b);
    qkv_gemm<<<dim3(NTOK/64, 12), 256>>>(wq, wk, wv);
    attn_kernel<<<dim3(TT/64, BB*HH), 128, ATTN_SMEM_BYTES>>>(
        lq1, lk1, lq2, lk2, sig_s, sig_n, hnw, hnb);
    out_gemm<<<dim3(NTOK/64, 2), 256>>>(wo, tokens, out);
}